// round 3
// baseline (speedup 1.0000x reference)
#include <cuda_runtime.h>

#define NI 128
#define NP 2000
#define MG 100
#define NA (NP + MG)          // 2100
#define NS 512
#define MAXPOS 128
#define NUMNEG 384
#define SORTN 4096
#define NT 512
#define CHUNK ((NA + NT - 1) / NT)   // 5

__device__ __forceinline__ unsigned long long onehot_cls(int c) {
    // packed counters: class3 -> bits[42..], class2 -> bits[21..], class0 -> bits[0..]
    int sh = (c == 3) ? 42 : (c == 2) ? 21 : 0;
    return 1ull << sh;
}

__global__ __launch_bounds__(NT)
void rcnn_sampler_kernel(const float* __restrict__ g_rois,    // [NI, NP, 4]
                         const float* __restrict__ g_scores,  // [NI, NP, 1]
                         const float* __restrict__ g_gt,      // [NI, MG, 4]
                         const float* __restrict__ g_rand,    // [NI, NA]
                         float* __restrict__ out)             // rois | samples | matches
{
    const int img = blockIdx.x;
    const int tid = threadIdx.x;

    __shared__ float s_gt[MG * 4];
    __shared__ float s_gta[MG];
    __shared__ unsigned long long s_key[SORTN];
    __shared__ unsigned char s_cls[NA];
    __shared__ short s_amax[NA];
    __shared__ unsigned long long s_wsum[NT / 32];
    __shared__ unsigned long long s_totals;
    __shared__ unsigned long long s_e;

    // ---- load gt boxes + areas ----
    const float* gtp = g_gt + (size_t)img * MG * 4;
    for (int i = tid; i < MG * 4; i += NT) s_gt[i] = gtp[i];
    __syncthreads();
    for (int k = tid; k < MG; k += NT) {
        float x1 = s_gt[k * 4 + 0], y1 = s_gt[k * 4 + 1];
        float x2 = s_gt[k * 4 + 2], y2 = s_gt[k * 4 + 3];
        s_gta[k] = fmaxf(x2 - x1, 0.f) * fmaxf(y2 - y1, 0.f);
    }

    // ---- build sort keys: (rand_bits << 32) | original_index ----
    // rand in [0,1): positive floats -> bit pattern is order-preserving.
    // Embedded index makes ties stable, matching jnp.argsort exactly.
    const float* rp = g_rand + (size_t)img * NA;
    for (int i = tid; i < SORTN; i += NT) {
        if (i < NA) {
            unsigned int b = __float_as_uint(rp[i]);
            s_key[i] = ((unsigned long long)b << 32) | (unsigned int)i;
        } else {
            s_key[i] = ~0ull;  // pad to power-of-two, sorts to the end
        }
    }
    __syncthreads();

    // ---- classify each of the 2100 boxes ----
    const float4* roisp = (const float4*)(g_rois + (size_t)img * NP * 4);
    const float*  scp   = g_scores + (size_t)img * NP;
    for (int i = tid; i < NA; i += NT) {
        float4 b;
        float score;
        if (i < NP) {
            b = roisp[i];
            score = scp[i];
        } else {
            int k = i - NP;
            b = make_float4(s_gt[k * 4 + 0], s_gt[k * 4 + 1],
                            s_gt[k * 4 + 2], s_gt[k * 4 + 3]);
            score = 1.0f;
        }
        float area_a = fmaxf(b.z - b.x, 0.f) * fmaxf(b.w - b.y, 0.f);
        float best = -1.f;
        int arg = 0;
        #pragma unroll 4
        for (int k = 0; k < MG; ++k) {
            float gx1 = s_gt[k * 4 + 0], gy1 = s_gt[k * 4 + 1];
            float gx2 = s_gt[k * 4 + 2], gy2 = s_gt[k * 4 + 3];
            float w = fminf(b.z, gx2) - fmaxf(b.x, gx1);
            float h = fminf(b.w, gy2) - fmaxf(b.y, gy1);
            float inter = fmaxf(w, 0.f) * fmaxf(h, 0.f);
            float uni = area_a + s_gta[k] - inter;
            float iou = (uni > 0.f) ? __fdiv_rn(inter, uni) : 0.f;  // IEEE div: match JAX
            if (iou > best) { best = iou; arg = k; }                // first-max == jnp.argmax
        }
        // mask=2; score<0 -> 0; iou_max>=0.5 -> 3 (overrides)
        int c = (best >= 0.5f) ? 3 : ((score < 0.f) ? 0 : 2);
        s_cls[i]  = (unsigned char)c;
        s_amax[i] = (short)arg;
    }
    __syncthreads();

    // ---- bitonic sort of 4096 u64 keys (ascending) ----
    for (unsigned int kk = 2; kk <= SORTN; kk <<= 1) {
        for (unsigned int ss = kk >> 1; ss > 0; ss >>= 1) {
            #pragma unroll
            for (unsigned int i = tid; i < SORTN; i += NT) {
                unsigned int ixj = i ^ ss;
                if (ixj > i) {
                    unsigned long long a = s_key[i];
                    unsigned long long c2 = s_key[ixj];
                    bool up = ((i & kk) == 0);
                    if ((a > c2) == up) { s_key[i] = c2; s_key[ixj] = a; }
                }
            }
            __syncthreads();
        }
    }

    // ---- packed per-class stable-rank scan over the permuted sequence ----
    unsigned long long loc = 0;
    const int j0 = tid * CHUNK;
    const int j1 = min(j0 + CHUNK, NA);
    for (int j = j0; j < j1; ++j) {
        unsigned int idx = (unsigned int)(s_key[j] & 0xFFFFFFFFu);
        loc += onehot_cls(s_cls[idx]);
    }
    unsigned long long v = loc;
    const unsigned int lane = tid & 31, wid = tid >> 5;
    #pragma unroll
    for (int o = 1; o < 32; o <<= 1) {
        unsigned long long n = __shfl_up_sync(0xFFFFFFFFu, v, o);
        if (lane >= (unsigned)o) v += n;
    }
    if (lane == 31) s_wsum[wid] = v;
    __syncthreads();
    if (tid == 0) {
        unsigned long long run = 0;
        #pragma unroll
        for (int w = 0; w < NT / 32; ++w) {
            unsigned long long t = s_wsum[w];
            s_wsum[w] = run;
            run += t;
        }
        s_totals = run;
    }
    __syncthreads();
    const unsigned long long excl = s_wsum[wid] + (v - loc);

    // counts for j < MAXPOS (thread owning j==MAXPOS's chunk computes it)
    {
        const int te = MAXPOS / CHUNK;  // chunk start te*CHUNK <= MAXPOS
        if (tid == te) {
            unsigned long long ee = excl;
            for (int j = te * CHUNK; j < MAXPOS; ++j) {
                unsigned int idx = (unsigned int)(s_key[j] & 0xFFFFFFFFu);
                ee += onehot_cls(s_cls[idx]);
            }
            s_e = ee;
        }
    }
    __syncthreads();

    // ---- closed-form slot assignment ----
    const unsigned long long M21 = (1ull << 21) - 1;
    const unsigned long long tot = s_totals, ev = s_e;
    const int c3  = (int)((tot >> 42) & M21);
    const int c2t = (int)((tot >> 21) & M21);
    const int e3  = (int)((ev  >> 42) & M21);
    const int e2  = (int)((ev  >> 21) & M21);
    const int e0  = (int)( ev         & M21);
    const int d2 = c2t - e2, d3 = c3 - e3;

    int r3 = (int)((excl >> 42) & M21);
    int r2 = (int)((excl >> 21) & M21);
    int r0 = (int)( excl         & M21);

    float* out_rois    = out;
    float* out_samples = out + (size_t)NI * NS * 4;
    float* out_matches = out_samples + (size_t)NI * NS;

    for (int j = j0; j < j1; ++j) {
        unsigned int idx = (unsigned int)(s_key[j] & 0xFFFFFFFFu);
        int c = s_cls[idx];
        int r;
        if (c == 3)      r = r3++;
        else if (c == 2) r = r2++;
        else             r = r0++;

        // top partition: priority 3 > 2 > 0, stable in j, first MAXPOS
        int tb = (c == 3) ? 0 : (c == 2) ? c3 : (c3 + c2t);
        int pos = tb + r;
        int slot1 = (pos < MAXPOS) ? pos : -1;

        // bottom partition: among j>=MAXPOS, priority 2 > 3 > 0, first NUMNEG
        int slot2 = -1;
        if (j >= MAXPOS) {
            int ec = (c == 3) ? e3 : (c == 2) ? e2 : e0;
            int bb = (c == 2) ? 0 : (c == 3) ? d2 : (d2 + d3);
            int pos2 = bb + (r - ec);
            if (pos2 < NUMNEG) slot2 = MAXPOS + pos2;
        }

        if (slot1 >= 0 || slot2 >= 0) {
            float4 b;
            if (idx < NP) {
                b = roisp[idx];
            } else {
                int k = idx - NP;
                b = make_float4(s_gt[k * 4 + 0], s_gt[k * 4 + 1],
                                s_gt[k * 4 + 2], s_gt[k * 4 + 3]);
            }
            float sval = (c == 3) ? 1.f : (c == 2) ? -1.f : 0.f;
            float mval = (float)s_amax[idx];
            if (slot1 >= 0) {
                size_t o = (size_t)img * NS + slot1;
                ((float4*)out_rois)[o] = b;
                out_samples[o] = sval;
                out_matches[o] = mval;
            }
            if (slot2 >= 0) {
                size_t o = (size_t)img * NS + slot2;
                ((float4*)out_rois)[o] = b;
                out_samples[o] = sval;
                out_matches[o] = mval;
            }
        }
    }
}

extern "C" void kernel_launch(void* const* d_in, const int* in_sizes, int n_in,
                              void* d_out, int out_size) {
    const float* rois   = (const float*)d_in[0];  // [128, 2000, 4]
    const float* scores = (const float*)d_in[1];  // [128, 2000, 1]
    const float* gt     = (const float*)d_in[2];  // [128, 100, 4]
    const float* rnd    = (const float*)d_in[3];  // [128, 2100]
    float* out = (float*)d_out;

    rcnn_sampler_kernel<<<NI, NT>>>(rois, scores, gt, rnd, out);
}

// round 4
// speedup vs baseline: 2.9539x; 2.9539x over previous
#include <cuda_runtime.h>

typedef unsigned long long u64;

#define NI 128
#define NP 2000
#define MG 100
#define NA (NP + MG)          // 2100
#define NS 512
#define MAXPOS 128
#define NUMNEG 384
#define SORTN 4096
#define NT 512

__device__ __forceinline__ void cex(u64 &a, u64 &b, bool up) {
    if ((a > b) == up) { u64 t = a; a = b; b = t; }
}

// 3-stage bitonic merge of 8 register elements, uniform direction
__device__ __forceinline__ void merge8(u64 *k, bool up) {
    cex(k[0],k[4],up); cex(k[1],k[5],up); cex(k[2],k[6],up); cex(k[3],k[7],up);
    cex(k[0],k[2],up); cex(k[1],k[3],up); cex(k[4],k[6],up); cex(k[5],k[7],up);
    cex(k[0],k[1],up); cex(k[2],k[3],up); cex(k[4],k[5],up); cex(k[6],k[7],up);
}

// cross-thread compare-exchange within a warp via shfl.xor
__device__ __forceinline__ void shfl_pass(u64 *k, int d, bool keepMin) {
    #pragma unroll
    for (int e = 0; e < 8; ++e) {
        u64 p  = __shfl_xor_sync(0xFFFFFFFFu, k[e], d);
        u64 lo = k[e] < p ? k[e] : p;
        u64 hi = k[e] < p ? p : k[e];
        k[e] = keepMin ? lo : hi;
    }
}

__global__ __launch_bounds__(NT)
void rcnn_sampler_kernel(const float4* __restrict__ g_rois,   // [NI, NP]
                         const float*  __restrict__ g_scores, // [NI, NP]
                         const float4* __restrict__ g_gt,     // [NI, MG]
                         const float*  __restrict__ g_rand,   // [NI, NA]
                         float* __restrict__ out)
{
    const int img = blockIdx.x;
    const int tid = threadIdx.x;
    const int base = tid << 3;   // first of this thread's 8 sort slots

    __shared__ float4 s_gt4[MG];
    __shared__ float4 s_vbox[MG];
    __shared__ float  s_varea[MG];
    __shared__ int    s_vidx[MG];
    __shared__ int    s_V;
    __shared__ u64    s_key[SORTN];
    __shared__ unsigned char s_cls[NA];   // shift amount: 42=pos, 21=neg-cand, 0=ignore
    __shared__ short  s_amax[NA];
    __shared__ u64    s_wsum[NT / 32];
    __shared__ u64    s_totals, s_e;

    // ---- load gt boxes ----
    const float4* gtp = g_gt + (size_t)img * MG;
    if (tid < MG) s_gt4[tid] = gtp[tid];

    // ---- build sort keys in REGISTERS: (rand_bits << 32) | idx ----
    // rand in [0,1): positive float bit-pattern is order-preserving.
    // Embedded idx makes ties stable, matching jnp.argsort exactly.
    u64 k[8];
    const float* rp = g_rand + (size_t)img * NA;
    #pragma unroll
    for (int e = 0; e < 8; ++e) {
        int i = base + e;
        if (i < NA) {
            unsigned int b = __float_as_uint(rp[i]);
            k[e] = ((u64)b << 32) | (unsigned int)i;
        } else {
            k[e] = ~0ull;  // pad sorts to the end
        }
    }
    __syncthreads();

    // ---- compact valid (nonzero-area) gt boxes ----
    // Zero-area gt gives IoU == 0.0f exactly vs every box (clip algebra),
    // so skipping them is bit-exact given best=0 / arg=0 init.
    if (tid == 0) {
        int v = 0;
        for (int g = 0; g < MG; ++g) {
            float4 b = s_gt4[g];
            float ar = fmaxf(b.z - b.x, 0.f) * fmaxf(b.w - b.y, 0.f);
            if (ar > 0.f) { s_vbox[v] = b; s_varea[v] = ar; s_vidx[v] = g; ++v; }
        }
        s_V = v;
    }
    __syncthreads();
    const int V = s_V;

    // ---- classify all 2100 boxes ----
    const float*  scp   = g_scores + (size_t)img * NP;
    const float4* roisp = g_rois   + (size_t)img * NP;
    for (int i = tid; i < NA; i += NT) {
        float4 b; float score;
        if (i < NP) { b = roisp[i]; score = scp[i]; }
        else        { b = s_gt4[i - NP]; score = 1.0f; }
        float area_a = fmaxf(b.z - b.x, 0.f) * fmaxf(b.w - b.y, 0.f);
        float best = 0.f; int arg = 0;   // argmax of all-zero row == 0 (ref semantics)
        for (int m = 0; m < V; ++m) {
            float4 g = s_vbox[m];
            float w = fminf(b.z, g.z) - fmaxf(b.x, g.x);
            float h = fminf(b.w, g.w) - fmaxf(b.y, g.y);
            if (w > 0.f && h > 0.f) {          // inter>0 ⇒ union>0; iou==0 can't beat best>=0
                float inter = w * h;
                float uni = area_a + s_varea[m] - inter;
                float iou = __fdiv_rn(inter, uni);   // IEEE div: bit-match JAX
                if (iou > best) { best = iou; arg = s_vidx[m]; }  // first-max == jnp.argmax
            }
        }
        s_cls[i]  = (best >= 0.5f) ? 42 : ((score < 0.f) ? 0 : 21);
        s_amax[i] = (short)arg;
    }
    // (classify writes are fenced by the sort's first __syncthreads below)

    // ======== bitonic sort of 4096 u64, ascending ========
    // kk = 2, 4 (per-element directions), kk = 8 (per-thread direction)
    cex(k[0],k[1],true);  cex(k[2],k[3],false); cex(k[4],k[5],true);  cex(k[6],k[7],false);
    cex(k[0],k[2],true);  cex(k[1],k[3],true);  cex(k[4],k[6],false); cex(k[5],k[7],false);
    cex(k[0],k[1],true);  cex(k[2],k[3],true);  cex(k[4],k[5],false); cex(k[6],k[7],false);
    merge8(k, (tid & 1) == 0);

    // kk = 16..256: shfl exchanges (stride/8 = 1..16 lanes) + register merge
    #pragma unroll
    for (int kk = 16; kk <= 256; kk <<= 1) {
        bool up = ((base & kk) == 0);
        #pragma unroll
        for (int ss = kk >> 1; ss >= 8; ss >>= 1) {
            int d = ss >> 3;
            shfl_pass(k, d, up != ((tid & d) != 0));
        }
        merge8(k, up);
    }

    // kk = 512..4096: smem for ss>=256, then shfl + register tail
    #pragma unroll
    for (int kk = 512; kk <= SORTN; kk <<= 1) {
        #pragma unroll
        for (int e = 0; e < 8; ++e) s_key[base + e] = k[e];
        __syncthreads();
        for (int ss = kk >> 1; ss >= 256; ss >>= 1) {
            #pragma unroll
            for (int p = tid; p < SORTN / 2; p += NT) {
                int i = ((p & ~(ss - 1)) << 1) | (p & (ss - 1));
                int j = i | ss;
                bool up = ((i & kk) == 0);
                u64 a = s_key[i], c2 = s_key[j];
                if ((a > c2) == up) { s_key[i] = c2; s_key[j] = a; }
            }
            __syncthreads();
        }
        #pragma unroll
        for (int e = 0; e < 8; ++e) k[e] = s_key[base + e];
        bool up = ((base & kk) == 0);
        #pragma unroll
        for (int ss = 128; ss >= 8; ss >>= 1) {
            int d = ss >> 3;
            shfl_pass(k, d, up != ((tid & d) != 0));
        }
        merge8(k, up);
    }
    // sorted sequence now lives in registers: position j = tid*8+e

    // ---- packed per-class stable-rank scan (21-bit fields in one u64) ----
    u64 loc = 0;
    #pragma unroll
    for (int e = 0; e < 8; ++e) {
        int j = base + e;
        if (j < NA) {
            unsigned int idx = (unsigned int)k[e];
            loc += 1ull << s_cls[idx];
        }
    }
    u64 v = loc;
    const unsigned int lane = tid & 31, wd = tid >> 5;
    #pragma unroll
    for (int o = 1; o < 32; o <<= 1) {
        u64 n = __shfl_up_sync(0xFFFFFFFFu, v, o);
        if (lane >= (unsigned)o) v += n;
    }
    if (lane == 31) s_wsum[wd] = v;
    __syncthreads();
    if (tid == 0) {
        u64 run = 0;
        #pragma unroll
        for (int w = 0; w < NT / 32; ++w) { u64 t2 = s_wsum[w]; s_wsum[w] = run; run += t2; }
        s_totals = run;
    }
    __syncthreads();
    const u64 excl = s_wsum[wd] + (v - loc);
    if (tid == MAXPOS / 8) s_e = excl;   // MAXPOS=128 boundary is exactly thread 16's start
    __syncthreads();

    // ---- closed-form slot assignment ----
    const u64 M21 = (1ull << 21) - 1;
    const u64 tot = s_totals, ev = s_e;
    const int c3  = (int)((tot >> 42) & M21);
    const int c2t = (int)((tot >> 21) & M21);
    const int e3  = (int)((ev  >> 42) & M21);
    const int e2  = (int)((ev  >> 21) & M21);
    const int e0  = (int)( ev         & M21);
    const int d2 = c2t - e2, d3 = c3 - e3;

    int r3 = (int)((excl >> 42) & M21);
    int r2 = (int)((excl >> 21) & M21);
    int r0 = (int)( excl         & M21);

    float* out_rois    = out;
    float* out_samples = out + (size_t)NI * NS * 4;
    float* out_matches = out_samples + (size_t)NI * NS;

    #pragma unroll
    for (int e = 0; e < 8; ++e) {
        int j = base + e;
        if (j >= NA) break;
        unsigned int idx = (unsigned int)k[e];
        int sh = s_cls[idx];
        int r;
        if (sh == 42)      r = r3++;
        else if (sh == 21) r = r2++;
        else               r = r0++;

        // top partition: priority 3 > 2 > 0, stable in j, first MAXPOS
        int tb = (sh == 42) ? 0 : (sh == 21 ? c3 : (c3 + c2t));
        int pos = tb + r;
        int slot1 = (pos < MAXPOS) ? pos : -1;

        // bottom partition: among j>=MAXPOS, priority 2 > 3 > 0, first NUMNEG
        int slot2 = -1;
        if (j >= MAXPOS) {
            int ec = (sh == 42) ? e3 : (sh == 21 ? e2 : e0);
            int bb = (sh == 21) ? 0 : (sh == 42 ? d2 : (d2 + d3));
            int pos2 = bb + (r - ec);
            if (pos2 < NUMNEG) slot2 = MAXPOS + pos2;
        }

        if (slot1 >= 0 || slot2 >= 0) {
            float4 b = (idx < NP) ? roisp[idx] : s_gt4[idx - NP];
            float sval = (sh == 42) ? 1.f : (sh == 21 ? -1.f : 0.f);
            float mval = (float)s_amax[idx];
            if (slot1 >= 0) {
                size_t o = (size_t)img * NS + slot1;
                ((float4*)out_rois)[o] = b;
                out_samples[o] = sval;
                out_matches[o] = mval;
            }
            if (slot2 >= 0) {
                size_t o = (size_t)img * NS + slot2;
                ((float4*)out_rois)[o] = b;
                out_samples[o] = sval;
                out_matches[o] = mval;
            }
        }
    }
}

extern "C" void kernel_launch(void* const* d_in, const int* in_sizes, int n_in,
                              void* d_out, int out_size) {
    const float4* rois   = (const float4*)d_in[0];  // [128, 2000, 4]
    const float*  scores = (const float*)d_in[1];   // [128, 2000, 1]
    const float4* gt     = (const float4*)d_in[2];  // [128, 100, 4]
    const float*  rnd    = (const float*)d_in[3];   // [128, 2100]
    float* out = (float*)d_out;

    rcnn_sampler_kernel<<<NI, NT>>>(rois, scores, gt, rnd, out);
}

// round 5
// speedup vs baseline: 3.7329x; 1.2637x over previous
#include <cuda_runtime.h>

typedef unsigned long long u64;

#define NI 128
#define NP 2000
#define MG 100
#define NA (NP + MG)          // 2100
#define NS 512
#define MAXPOS 128
#define NUMNEG 384
#define SORTN 4096
#define NT 1024
#define E 4                   // keys per thread

__device__ __forceinline__ void cex(u64 &a, u64 &b, bool up) {
    if ((a > b) == up) { u64 t = a; a = b; b = t; }
}

// bitonic merge of 4 register elements, uniform direction
__device__ __forceinline__ void merge4(u64 *k, bool up) {
    cex(k[0],k[2],up); cex(k[1],k[3],up);
    cex(k[0],k[1],up); cex(k[2],k[3],up);
}

// cross-thread compare-exchange within a warp via shfl.xor
__device__ __forceinline__ void shfl_pass(u64 *k, int d, bool keepMin) {
    #pragma unroll
    for (int e = 0; e < E; ++e) {
        u64 p  = __shfl_xor_sync(0xFFFFFFFFu, k[e], d);
        u64 lo = k[e] < p ? k[e] : p;
        u64 hi = k[e] < p ? p : k[e];
        k[e] = keepMin ? lo : hi;
    }
}

__global__ __launch_bounds__(NT)
void rcnn_sampler_kernel(const float4* __restrict__ g_rois,   // [NI, NP]
                         const float*  __restrict__ g_scores, // [NI, NP]
                         const float4* __restrict__ g_gt,     // [NI, MG]
                         const float*  __restrict__ g_rand,   // [NI, NA]
                         float* __restrict__ out)
{
    const int img = blockIdx.x;
    const int tid = threadIdx.x;
    const int base = tid << 2;   // first of this thread's 4 sort slots

    __shared__ float4 s_gt4[MG];
    __shared__ float4 s_vbox[MG];
    __shared__ float  s_varea[MG];
    __shared__ int    s_vidx[MG];
    __shared__ int    s_V;
    __shared__ int    s_wcnt[4];
    __shared__ u64    s_key[SORTN];
    __shared__ unsigned char s_cls[NA];   // shift: 42=pos, 21=neg-cand, 0=ignore
    __shared__ short  s_amax[NA];
    __shared__ u64    s_wsum[NT / 32];
    __shared__ u64    s_totals, s_e;

    // ---- load gt boxes; per-thread validity (nonzero area) ----
    // Zero-area gt gives IoU == 0.0f exactly vs every box (clip algebra),
    // so skipping them is bit-exact given best=0 / arg=0 init.
    float4 myb; float myar = 0.f; bool myval = false;
    if (tid < MG) {
        myb = g_gt[(size_t)img * MG + tid];
        s_gt4[tid] = myb;
        myar = fmaxf(myb.z - myb.x, 0.f) * fmaxf(myb.w - myb.y, 0.f);
        myval = myar > 0.f;
    }
    unsigned bal = __ballot_sync(0xFFFFFFFFu, myval);
    if ((tid & 31) == 0 && tid < 128) s_wcnt[tid >> 5] = __popc(bal);

    // ---- build sort keys in REGISTERS: (rand_bits << 32) | idx ----
    // rand in [0,1): positive float bit-pattern is order-preserving.
    // Embedded idx makes ties stable, matching jnp.argsort exactly.
    u64 k[E];
    const float* rp = g_rand + (size_t)img * NA;
    #pragma unroll
    for (int e = 0; e < E; ++e) {
        int i = base + e;
        if (i < NA) {
            unsigned int b = __float_as_uint(rp[i]);
            k[e] = ((u64)b << 32) | (unsigned int)i;
        } else {
            k[e] = ~0ull;  // pad sorts to the end
        }
    }
    __syncthreads();

    // ---- scatter compacted valid gt (order-preserving) ----
    if (myval) {
        int wno = tid >> 5;
        int off = __popc(bal & ((1u << (tid & 31)) - 1));
        for (int w = 0; w < wno; ++w) off += s_wcnt[w];
        s_vbox[off] = myb; s_varea[off] = myar; s_vidx[off] = tid;
    }
    if (tid == 0) s_V = s_wcnt[0] + s_wcnt[1] + s_wcnt[2] + s_wcnt[3];
    __syncthreads();
    const int V = s_V;

    // ---- classify all 2100 boxes ----
    const float*  scp   = g_scores + (size_t)img * NP;
    const float4* roisp = g_rois   + (size_t)img * NP;
    for (int i = tid; i < NA; i += NT) {
        float4 b; float score;
        if (i < NP) { b = roisp[i]; score = scp[i]; }
        else        { b = s_gt4[i - NP]; score = 1.0f; }
        float area_a = fmaxf(b.z - b.x, 0.f) * fmaxf(b.w - b.y, 0.f);
        float best = 0.f; int arg = 0;   // argmax of all-zero row == 0 (ref semantics)
        for (int m = 0; m < V; ++m) {
            float4 g = s_vbox[m];
            float w = fminf(b.z, g.z) - fmaxf(b.x, g.x);
            float h = fminf(b.w, g.w) - fmaxf(b.y, g.y);
            if (w > 0.f && h > 0.f) {        // inter>0 ⇒ union>0; iou==0 can't beat best>=0
                float inter = w * h;
                float uni = area_a + s_varea[m] - inter;
                float iou = __fdiv_rn(inter, uni);   // IEEE div: bit-match JAX
                if (iou > best) { best = iou; arg = s_vidx[m]; }  // first-max == jnp.argmax
            }
        }
        s_cls[i]  = (best >= 0.5f) ? 42 : ((score < 0.f) ? 0 : 21);
        s_amax[i] = (short)arg;
    }
    // (classify smem writes are fenced by the sort's first __syncthreads below)

    // ======== bitonic sort of 4096 u64, ascending ========
    // kk = 2 (per-element dirs), kk = 4 (per-thread dir)
    cex(k[0],k[1],true); cex(k[2],k[3],false);
    merge4(k, (tid & 1) == 0);

    // kk = 8..128: in-warp shfl exchanges + register merge
    #pragma unroll
    for (int kk = 8; kk <= 128; kk <<= 1) {
        bool up = ((base & kk) == 0);
        #pragma unroll
        for (int ss = kk >> 1; ss >= 4; ss >>= 1) {
            int d = ss >> 2;
            shfl_pass(k, d, up != ((tid & d) != 0));
        }
        merge4(k, up);
    }

    // kk = 256..4096: smem for ss>=128, then in-warp shfl + register tail
    #pragma unroll
    for (int kk = 256; kk <= SORTN; kk <<= 1) {
        #pragma unroll
        for (int e = 0; e < E; ++e) s_key[base + e] = k[e];
        __syncthreads();
        for (int ss = kk >> 1; ss >= 128; ss >>= 1) {
            #pragma unroll
            for (int p = tid; p < SORTN / 2; p += NT) {
                int i = ((p & ~(ss - 1)) << 1) | (p & (ss - 1));
                int j = i | ss;
                bool up2 = ((i & kk) == 0);
                u64 a = s_key[i], c2 = s_key[j];
                if ((a > c2) == up2) { s_key[i] = c2; s_key[j] = a; }
            }
            __syncthreads();
        }
        #pragma unroll
        for (int e = 0; e < E; ++e) k[e] = s_key[base + e];
        bool up = ((base & kk) == 0);
        #pragma unroll
        for (int ss = 64; ss >= 4; ss >>= 1) {
            int d = ss >> 2;
            shfl_pass(k, d, up != ((tid & d) != 0));
        }
        merge4(k, up);
    }
    // sorted sequence now lives in registers: position j = tid*4+e

    // ---- packed per-class stable-rank scan (21-bit fields in one u64) ----
    u64 loc = 0;
    #pragma unroll
    for (int e = 0; e < E; ++e) {
        int j = base + e;
        if (j < NA) {
            unsigned int idx = (unsigned int)k[e];
            loc += 1ull << s_cls[idx];
        }
    }
    u64 v = loc;
    const unsigned int lane = tid & 31, wd = tid >> 5;
    #pragma unroll
    for (int o = 1; o < 32; o <<= 1) {
        u64 n = __shfl_up_sync(0xFFFFFFFFu, v, o);
        if (lane >= (unsigned)o) v += n;
    }
    if (lane == 31) s_wsum[wd] = v;
    __syncthreads();
    if (tid == 0) {
        u64 run = 0;
        #pragma unroll
        for (int w = 0; w < NT / 32; ++w) { u64 t2 = s_wsum[w]; s_wsum[w] = run; run += t2; }
        s_totals = run;
    }
    __syncthreads();
    const u64 excl = s_wsum[wd] + (v - loc);
    if (tid == MAXPOS / E) s_e = excl;   // MAXPOS=128 boundary = thread 32's start
    __syncthreads();

    // ---- closed-form slot assignment ----
    const u64 M21 = (1ull << 21) - 1;
    const u64 tot = s_totals, ev = s_e;
    const int c3  = (int)((tot >> 42) & M21);
    const int c2t = (int)((tot >> 21) & M21);
    const int e3  = (int)((ev  >> 42) & M21);
    const int e2  = (int)((ev  >> 21) & M21);
    const int e0  = (int)( ev         & M21);
    const int d2 = c2t - e2, d3 = c3 - e3;

    int r3 = (int)((excl >> 42) & M21);
    int r2 = (int)((excl >> 21) & M21);
    int r0 = (int)( excl         & M21);

    float* out_rois    = out;
    float* out_samples = out + (size_t)NI * NS * 4;
    float* out_matches = out_samples + (size_t)NI * NS;

    #pragma unroll
    for (int e = 0; e < E; ++e) {
        int j = base + e;
        if (j >= NA) break;
        unsigned int idx = (unsigned int)k[e];
        int sh = s_cls[idx];
        int r;
        if (sh == 42)      r = r3++;
        else if (sh == 21) r = r2++;
        else               r = r0++;

        // top partition: priority 3 > 2 > 0, stable in j, first MAXPOS
        int tb = (sh == 42) ? 0 : (sh == 21 ? c3 : (c3 + c2t));
        int pos = tb + r;
        int slot1 = (pos < MAXPOS) ? pos : -1;

        // bottom partition: among j>=MAXPOS, priority 2 > 3 > 0, first NUMNEG
        int slot2 = -1;
        if (j >= MAXPOS) {
            int ec = (sh == 42) ? e3 : (sh == 21 ? e2 : e0);
            int bb = (sh == 21) ? 0 : (sh == 42 ? d2 : (d2 + d3));
            int pos2 = bb + (r - ec);
            if (pos2 < NUMNEG) slot2 = MAXPOS + pos2;
        }

        if (slot1 >= 0 || slot2 >= 0) {
            float4 b = (idx < NP) ? roisp[idx] : s_gt4[idx - NP];
            float sval = (sh == 42) ? 1.f : (sh == 21 ? -1.f : 0.f);
            float mval = (float)s_amax[idx];
            if (slot1 >= 0) {
                size_t o = (size_t)img * NS + slot1;
                ((float4*)out_rois)[o] = b;
                out_samples[o] = sval;
                out_matches[o] = mval;
            }
            if (slot2 >= 0) {
                size_t o = (size_t)img * NS + slot2;
                ((float4*)out_rois)[o] = b;
                out_samples[o] = sval;
                out_matches[o] = mval;
            }
        }
    }
}

extern "C" void kernel_launch(void* const* d_in, const int* in_sizes, int n_in,
                              void* d_out, int out_size) {
    const float4* rois   = (const float4*)d_in[0];  // [128, 2000, 4]
    const float*  scores = (const float*)d_in[1];   // [128, 2000, 1]
    const float4* gt     = (const float4*)d_in[2];  // [128, 100, 4]
    const float*  rnd    = (const float*)d_in[3];   // [128, 2100]
    float* out = (float*)d_out;

    rcnn_sampler_kernel<<<NI, NT>>>(rois, scores, gt, rnd, out);
}

// round 6
// speedup vs baseline: 6.6565x; 1.7832x over previous
#include <cuda_runtime.h>

typedef unsigned long long u64;

#define NI 128
#define NP 2000
#define MG 100
#define NA (NP + MG)          // 2100
#define NS 512
#define MAXPOS 128
#define NUMNEG 384
#define NT 1024
#define NB 2048               // buckets
#define CHUNK 3               // ceil(NA / NT)
#define MAXEL 3               // max elements per thread (tid<52 have 3)

__global__ __launch_bounds__(NT)
void rcnn_sampler_kernel(const float4* __restrict__ g_rois,   // [NI, NP]
                         const float*  __restrict__ g_scores, // [NI, NP]
                         const float4* __restrict__ g_gt,     // [NI, MG]
                         const float*  __restrict__ g_rand,   // [NI, NA]
                         float* __restrict__ out)
{
    const int img = blockIdx.x;
    const int tid = threadIdx.x;

    __shared__ float4 s_gt4[MG];
    __shared__ float4 s_vbox[MG];
    __shared__ float  s_varea[MG];
    __shared__ int    s_vidx[MG];
    __shared__ int    s_V;
    __shared__ int    s_wcnt[4];
    __shared__ int    s_cnt[NB];          // histogram (counts)
    __shared__ int    s_off[NB];          // exclusive offsets -> ends after scatter
    __shared__ u64    s_skey[NA];         // sorted (rand_bits<<32 | idx)
    __shared__ unsigned char s_cls[NA];   // shift: 42=pos, 21=neg-cand, 0=ignore
    __shared__ short  s_amax[NA];
    __shared__ int    s_iwsum[NT / 32];
    __shared__ u64    s_wsum[NT / 32];
    __shared__ u64    s_totals, s_e;

    // ---- phase A: zero histogram, load gt, validity ballot, build keys ----
    s_cnt[tid] = 0; s_cnt[tid + NT] = 0;

    // Zero-area gt gives IoU == 0.0f exactly vs every box (clip algebra),
    // so skipping them is bit-exact given best=0 / arg=0 init.
    float4 myb; float myar = 0.f; bool myval = false;
    if (tid < MG) {
        myb = g_gt[(size_t)img * MG + tid];
        s_gt4[tid] = myb;
        myar = fmaxf(myb.z - myb.x, 0.f) * fmaxf(myb.w - myb.y, 0.f);
        myval = myar > 0.f;
    }
    unsigned bal = __ballot_sync(0xFFFFFFFFu, myval);
    if ((tid & 31) == 0 && tid < 128) s_wcnt[tid >> 5] = __popc(bal);

    // keys in registers: (rand_bits << 32) | idx. rand in [0,1): positive
    // float bit-pattern is order-preserving; embedded idx makes ties stable,
    // so sorting these u64s == jnp.argsort(rand) exactly.
    u64 myk[MAXEL]; int mybkt[MAXEL]; int nown = 0;
    const float* rp = g_rand + (size_t)img * NA;
    #pragma unroll
    for (int e = 0; e < MAXEL; ++e) {
        int i = tid + e * NT;
        if (i < NA) {
            float r = rp[i];
            myk[e] = ((u64)__float_as_uint(r) << 32) | (unsigned int)i;
            // uniform value -> uniform, order-preserving bucket (monotone fp ops)
            mybkt[e] = min((int)(r * (float)NB), NB - 1);
            ++nown;
        }
    }
    __syncthreads();

    // ---- phase B: gt compaction scatter + histogram ----
    if (myval) {
        int off = __popc(bal & ((1u << (tid & 31)) - 1));
        for (int w = 0; w < (tid >> 5); ++w) off += s_wcnt[w];
        s_vbox[off] = myb; s_varea[off] = myar; s_vidx[off] = tid;
    }
    if (tid == 0) s_V = s_wcnt[0] + s_wcnt[1] + s_wcnt[2] + s_wcnt[3];
    #pragma unroll
    for (int e = 0; e < MAXEL; ++e)
        if (e < nown) atomicAdd(&s_cnt[mybkt[e]], 1);
    __syncthreads();
    const int V = s_V;

    // ---- phase C1: classify all 2100 boxes ----
    const float*  scp   = g_scores + (size_t)img * NP;
    const float4* roisp = g_rois   + (size_t)img * NP;
    for (int i = tid; i < NA; i += NT) {
        float4 b; float score;
        if (i < NP) { b = roisp[i]; score = scp[i]; }
        else        { b = s_gt4[i - NP]; score = 1.0f; }
        float area_a = fmaxf(b.z - b.x, 0.f) * fmaxf(b.w - b.y, 0.f);
        float best = 0.f; int arg = 0;   // argmax of all-zero row == 0 (ref semantics)
        for (int m = 0; m < V; ++m) {
            float4 g = s_vbox[m];
            float w = fminf(b.z, g.z) - fmaxf(b.x, g.x);
            float h = fminf(b.w, g.w) - fmaxf(b.y, g.y);
            if (w > 0.f && h > 0.f) {        // inter>0 ⇒ union>0; iou==0 can't beat best>=0
                float inter = w * h;
                float uni = area_a + s_varea[m] - inter;
                float iou = __fdiv_rn(inter, uni);   // IEEE div: bit-match JAX
                if (iou > best) { best = iou; arg = s_vidx[m]; }  // first-max == jnp.argmax
            }
        }
        s_cls[i]  = (best >= 0.5f) ? 42 : ((score < 0.f) ? 0 : 21);
        s_amax[i] = (short)arg;
    }

    // ---- phase C2: exclusive scan of 2048 bucket counts ----
    const unsigned int lane = tid & 31, wd = tid >> 5;
    {
        int c0 = s_cnt[2 * tid], c1 = s_cnt[2 * tid + 1];
        int sum2 = c0 + c1;
        int vv = sum2;
        #pragma unroll
        for (int o = 1; o < 32; o <<= 1) {
            int n = __shfl_up_sync(0xFFFFFFFFu, vv, o);
            if (lane >= (unsigned)o) vv += n;
        }
        if (lane == 31) s_iwsum[wd] = vv;
        __syncthreads();
        if (tid == 0) {
            int run = 0;
            #pragma unroll
            for (int w = 0; w < NT / 32; ++w) { int t2 = s_iwsum[w]; s_iwsum[w] = run; run += t2; }
        }
        __syncthreads();
        int ex = s_iwsum[wd] + (vv - sum2);
        s_off[2 * tid] = ex;
        s_off[2 * tid + 1] = ex + c0;
    }
    __syncthreads();

    // ---- phase D: scatter into bucket slots (arrival order; fixed next) ----
    #pragma unroll
    for (int e = 0; e < MAXEL; ++e)
        if (e < nown) {
            int p = atomicAdd(&s_off[mybkt[e]], 1);   // s_off[b] becomes bucket END
            s_skey[p] = myk[e];
        }
    __syncthreads();

    // ---- phase E: per-bucket insertion sort (avg load ~1, max ~8) ----
    #pragma unroll
    for (int bb = tid; bb < NB; bb += NT) {
        int end = s_off[bb];
        int st  = end - s_cnt[bb];
        for (int a = st + 1; a < end; ++a) {
            u64 key = s_skey[a];
            int p = a - 1;
            while (p >= st && s_skey[p] > key) { s_skey[p + 1] = s_skey[p]; --p; }
            s_skey[p + 1] = key;
        }
    }
    __syncthreads();
    // s_skey[0..NA) is now the globally sorted stable order

    // ---- phase F: packed per-class stable-rank scan (21-bit fields / u64) ----
    const int j0 = tid * CHUNK;
    const int j1 = min(j0 + CHUNK, NA);
    u64 loc = 0;
    for (int j = j0; j < j1; ++j)
        loc += 1ull << s_cls[(unsigned int)s_skey[j]];
    u64 v = loc;
    #pragma unroll
    for (int o = 1; o < 32; o <<= 1) {
        u64 n = __shfl_up_sync(0xFFFFFFFFu, v, o);
        if (lane >= (unsigned)o) v += n;
    }
    if (lane == 31) s_wsum[wd] = v;
    __syncthreads();
    if (tid == 0) {
        u64 run = 0;
        #pragma unroll
        for (int w = 0; w < NT / 32; ++w) { u64 t2 = s_wsum[w]; s_wsum[w] = run; run += t2; }
        s_totals = run;
    }
    __syncthreads();
    const u64 excl = s_wsum[wd] + (v - loc);
    if (tid == MAXPOS / CHUNK) {                 // chunk containing j == 128
        u64 ee = excl;
        for (int j = (MAXPOS / CHUNK) * CHUNK; j < MAXPOS; ++j)
            ee += 1ull << s_cls[(unsigned int)s_skey[j]];
        s_e = ee;
    }
    __syncthreads();

    // ---- phase G: closed-form slot assignment + output ----
    const u64 M21 = (1ull << 21) - 1;
    const u64 tot = s_totals, ev = s_e;
    const int c3  = (int)((tot >> 42) & M21);
    const int c2t = (int)((tot >> 21) & M21);
    const int e3  = (int)((ev  >> 42) & M21);
    const int e2  = (int)((ev  >> 21) & M21);
    const int e0  = (int)( ev         & M21);
    const int d2 = c2t - e2, d3 = c3 - e3;

    int r3 = (int)((excl >> 42) & M21);
    int r2 = (int)((excl >> 21) & M21);
    int r0 = (int)( excl         & M21);

    float* out_rois    = out;
    float* out_samples = out + (size_t)NI * NS * 4;
    float* out_matches = out_samples + (size_t)NI * NS;

    for (int j = j0; j < j1; ++j) {
        unsigned int idx = (unsigned int)s_skey[j];
        int sh = s_cls[idx];
        int r;
        if (sh == 42)      r = r3++;
        else if (sh == 21) r = r2++;
        else               r = r0++;

        // top partition: priority 3 > 2 > 0, stable in j, first MAXPOS
        int tb = (sh == 42) ? 0 : (sh == 21 ? c3 : (c3 + c2t));
        int pos = tb + r;
        int slot1 = (pos < MAXPOS) ? pos : -1;

        // bottom partition: among j>=MAXPOS, priority 2 > 3 > 0, first NUMNEG
        int slot2 = -1;
        if (j >= MAXPOS) {
            int ec = (sh == 42) ? e3 : (sh == 21 ? e2 : e0);
            int bb = (sh == 21) ? 0 : (sh == 42 ? d2 : (d2 + d3));
            int pos2 = bb + (r - ec);
            if (pos2 < NUMNEG) slot2 = MAXPOS + pos2;
        }

        if (slot1 >= 0 || slot2 >= 0) {
            float4 b = (idx < NP) ? roisp[idx] : s_gt4[idx - NP];
            float sval = (sh == 42) ? 1.f : (sh == 21 ? -1.f : 0.f);
            float mval = (float)s_amax[idx];
            if (slot1 >= 0) {
                size_t o = (size_t)img * NS + slot1;
                ((float4*)out_rois)[o] = b;
                out_samples[o] = sval;
                out_matches[o] = mval;
            }
            if (slot2 >= 0) {
                size_t o = (size_t)img * NS + slot2;
                ((float4*)out_rois)[o] = b;
                out_samples[o] = sval;
                out_matches[o] = mval;
            }
        }
    }
}

extern "C" void kernel_launch(void* const* d_in, const int* in_sizes, int n_in,
                              void* d_out, int out_size) {
    const float4* rois   = (const float4*)d_in[0];  // [128, 2000, 4]
    const float*  scores = (const float*)d_in[1];   // [128, 2000, 1]
    const float4* gt     = (const float4*)d_in[2];  // [128, 100, 4]
    const float*  rnd    = (const float*)d_in[3];   // [128, 2100]
    float* out = (float*)d_out;

    rcnn_sampler_kernel<<<NI, NT>>>(rois, scores, gt, rnd, out);
}